// round 3
// baseline (speedup 1.0000x reference)
#include <cuda_runtime.h>
#include <cstdint>

// CTC forward loss — ONE WARP PER BATCH, register alphas, shfl exchange.
// B=256, T=512, C=128, L=64, S=129, blank=127.
// Deinterleaved states: even s=2j (blank, 2-way lse), odd s=2j+1 (label j, 3-way lse).
// lane j of group g holds even[32g+lane], odd[32g+lane]. lp for t+1 prefetched during step t.

#define CTC_B 256
#define CTC_T 512
#define CTC_C 128
#define CTC_L 64
#define BLANK (CTC_C - 1)
#define DEPTH 8
#define WPC 2                  // warps (=batches) per CTA
#define NEGINF (-1e30f)
#define EPS_F  (1e-7f)
#define FM 0xffffffffu

__device__ __forceinline__ void cp_async16(void* smem_dst, const void* gmem_src) {
    unsigned saddr = (unsigned)__cvta_generic_to_shared(smem_dst);
    asm volatile("cp.async.cg.shared.global [%0], [%1], 16;\n"
                 :: "r"(saddr), "l"(gmem_src) : "memory");
}
#define CP_COMMIT() asm volatile("cp.async.commit_group;\n" ::: "memory")
#define CP_WAIT(n)  asm volatile("cp.async.wait_group %0;\n" :: "n"(n) : "memory")

__device__ __forceinline__ float lse2(float a, float b) {
    float m = fmaxf(a, b);
    return m + __logf(__expf(a - m) + __expf(b - m));
}
__device__ __forceinline__ float lse3(float a, float b, float c) {
    float m = fmaxf(a, fmaxf(b, c));
    return m + __logf(__expf(a - m) + __expf(b - m) + __expf(c - m));
}

// TWO: states need lane-group 1 (l >= 32). E64: state s=128 needed (l == 64).
template<bool TWO, bool E64>
__device__ __forceinline__ void ctc_warp(
    const float* __restrict__ yb, float (*ring)[CTC_C],
    int lane, int l, int t_idx,
    int lab0, int lab1, bool sk0, bool sk1,
    float* __restrict__ outp)
{
    // ---- prologue: issue rows 0..DEPTH-1, one commit group per row ----
    #pragma unroll
    for (int r = 0; r < DEPTH; ++r) {
        cp_async16(&ring[r][lane * 4], yb + (size_t)r * CTC_C + lane * 4);
        CP_COMMIT();
    }
    CP_WAIT(DEPTH - 2);            // rows 0,1 complete
    __syncwarp();

    // lp(row0) + init alphas at t=0
    float lpb0  = __logf(ring[0][BLANK] + EPS_F);
    float lpo00 = __logf(ring[0][lab0] + EPS_F);
    float e0 = (lane == 0) ? lpb0  : NEGINF;   // even j=0 (blank)
    float o0 = (lane == 0) ? lpo00 : NEGINF;   // odd  j=0 (label 0)
    float e1 = NEGINF, o1 = NEGINF, e64v = NEGINF;

    float a_last = NEGINF, a_prev = NEGINF;
    if (t_idx == 0) {
        a_last = E64 ? e64v : __shfl_sync(FM, (l >= 32) ? e1 : e0, l & 31);
        float ov = ((l - 1) >= 32) ? o1 : o0;
        a_prev = __shfl_sync(FM, ov, (l - 1) & 31);
    }

    // lp_cur = lp(row1)
    float lpb_c  = __logf(ring[1][BLANK] + EPS_F);
    float lpo0_c = __logf(ring[1][lab0] + EPS_F);
    float lpo1_c = 0.0f;
    if (TWO) lpo1_c = __logf(ring[1][lab1] + EPS_F);

    for (int t = 1; t < CTC_T; ++t) {
        // keep DEPTH-1 rows in flight; slot (t-1)%DEPTH was last read 2 iters ago
        const int nr = t + DEPTH - 1;
        if (nr < CTC_T)
            cp_async16(&ring[nr & (DEPTH - 1)][lane * 4],
                       yb + (size_t)nr * CTC_C + lane * 4);
        CP_COMMIT();
        CP_WAIT(DEPTH - 3);        // guarantees row t+1 complete
        __syncwarp();

        // prefetch lp for step t+1 (off the alpha dependency chain;
        // at t=T-1 this reads a stale slot -> garbage, never used)
        const float* __restrict__ rn = ring[(t + 1) & (DEPTH - 1)];
        float lpb_n  = __logf(rn[BLANK] + EPS_F);
        float lpo0_n = __logf(rn[lab0] + EPS_F);
        float lpo1_n = 0.0f;
        if (TWO) lpo1_n = __logf(rn[lab1] + EPS_F);

        // shifted OLD odd values: odd[j-1]
        float om0 = __shfl_up_sync(FM, o0, 1);
        float o0_31 = __shfl_sync(FM, o0, 31);
        if (lane == 0) om0 = NEGINF;

        float om1 = 0.0f;
        if (TWO) {
            om1 = __shfl_up_sync(FM, o1, 1);
            if (lane == 0) om1 = o0_31;
        }
        float o1_31 = 0.0f;
        if (E64) o1_31 = __shfl_sync(FM, o1, 31);   // OLD odd[63]

        // updates
        float ne0 = lse2(e0, om0) + lpb_c;                          // even j: blank, never skips
        float no0 = lse3(o0, e0, sk0 ? om0 : NEGINF) + lpo0_c;      // odd j: 3-way
        float ne1 = e1, no1 = o1, ne64 = e64v;
        if (TWO) {
            ne1 = lse2(e1, om1) + lpb_c;
            no1 = lse3(o1, e1, sk1 ? om1 : NEGINF) + lpo1_c;
        }
        if (E64) ne64 = lse2(e64v, o1_31) + lpb_c;                  // even j=64

        e0 = ne0; o0 = no0; e1 = ne1; o1 = no1; e64v = ne64;
        lpb_c = lpb_n; lpo0_c = lpo0_n;
        if (TWO) lpo1_c = lpo1_n;

        if (t == t_idx) {
            a_last = E64 ? e64v : __shfl_sync(FM, (l >= 32) ? e1 : e0, l & 31);
            float ov = ((l - 1) >= 32) ? o1 : o0;
            a_prev = __shfl_sync(FM, ov, (l - 1) & 31);
        }
    }

    if (lane == 0) *outp = -lse2(a_last, a_prev);
}

__global__ __launch_bounds__(WPC * 32, 1)
void ctc_loss_kernel(const float* __restrict__ y_pred,
                     const int*   __restrict__ labels,
                     const int*   __restrict__ input_length,
                     const int*   __restrict__ label_length,
                     float*       __restrict__ out)
{
    __shared__ float rows[WPC][DEPTH][CTC_C];
    const int wid  = threadIdx.x >> 5;
    const int lane = threadIdx.x & 31;
    const int b = blockIdx.x * WPC + wid;
    const float* __restrict__ yb = y_pred + (size_t)b * CTC_T * CTC_C;

    const int l     = label_length[b];
    const int t_idx = input_length[b] - 1;

    // labels for odd states: group0 = labels[0..31], group1 = labels[32..63]
    const int lab0 = labels[b * CTC_L + lane];
    const int lab1 = labels[b * CTC_L + 32 + lane];
    const int lab0_31 = __shfl_sync(FM, lab0, 31);
    int lab0m = __shfl_up_sync(FM, lab0, 1);
    int lab1m = __shfl_up_sync(FM, lab1, 1);
    if (lane == 0) lab1m = lab0_31;
    const bool sk0 = (lane > 0) && (lab0 != lab0m);   // j=0: s=1 < 2 -> no skip
    const bool sk1 = (lab1 != lab1m);                 // j>=32: always s>=2

    if (l <= 31)
        ctc_warp<false, false>(yb, rows[wid], lane, l, t_idx, lab0, lab1, sk0, sk1, out + b);
    else if (l <= 63)
        ctc_warp<true, false>(yb, rows[wid], lane, l, t_idx, lab0, lab1, sk0, sk1, out + b);
    else
        ctc_warp<true, true>(yb, rows[wid], lane, l, t_idx, lab0, lab1, sk0, sk1, out + b);
}

extern "C" void kernel_launch(void* const* d_in, const int* in_sizes, int n_in,
                              void* d_out, int out_size) {
    const float* y_pred       = (const float*)d_in[0];
    const int*   labels       = (const int*)  d_in[1];
    const int*   input_length = (const int*)  d_in[2];
    const int*   label_length = (const int*)  d_in[3];
    float*       out          = (float*)d_out;

    ctc_loss_kernel<<<CTC_B / WPC, WPC * 32>>>(y_pred, labels, input_length, label_length, out);
}

// round 5
// speedup vs baseline: 2.6803x; 2.6803x over previous
#include <cuda_runtime.h>
#include <cstdint>

// CTC forward — one warp/batch, scaled-linear forward with PER-STATE scales.
// alpha[s] = v[s] * e^{c[s]}; c renormed every 8 steps to (running-max of L) - 40,
// which keeps every edge factor f = e^{c_src-c_dst} <= 1 (no overflow) and keeps
// states up to ~128 nats below their left-running max representable.
// Inner loop: FMA + shfl only (no MUFU).

#define CTC_B   256
#define CTC_T   512
#define CTC_C   128
#define CTC_L   64
#define BLANK   (CTC_C - 1)
#define WPC     2
#define MACRO   8
#define NMACRO  (CTC_T / MACRO)   // 64
#define EPS_F   1e-7f
#define FM      0xffffffffu
#define BIAS    40.0f

__device__ __forceinline__ void cp_async16(void* smem_dst, const void* gmem_src) {
    unsigned saddr = (unsigned)__cvta_generic_to_shared(smem_dst);
    asm volatile("cp.async.cg.shared.global [%0], [%1], 16;\n"
                 :: "r"(saddr), "l"(gmem_src) : "memory");
}
#define CP_COMMIT() asm volatile("cp.async.commit_group;\n" ::: "memory")
#define CP_WAIT(n)  asm volatile("cp.async.wait_group %0;\n" :: "n"(n) : "memory")

// inclusive running max over lanes (shfl_up returns own value for lane<d -> safe)
__device__ __forceinline__ float warp_runmax(float p) {
    #pragma unroll
    for (int d = 1; d < 32; d <<= 1)
        p = fmaxf(p, __shfl_up_sync(FM, p, d));
    return p;
}

template<bool TWO, bool E64>
__device__ __forceinline__ void ctc_warp(
    const float* __restrict__ yb,
    float (*ring)[MACRO][CTC_C],
    int lane, int l, int t_idx,
    int lab0, int lab1, float skm0, float skm1,
    float* __restrict__ outp)
{
    // prologue: macros 0,1 in flight (one commit group each)
    #pragma unroll
    for (int mb = 0; mb < 2; ++mb) {
        #pragma unroll
        for (int r = 0; r < MACRO; ++r)
            cp_async16(&ring[mb][r][lane * 4],
                       yb + (size_t)(mb * MACRO + r) * CTC_C + lane * 4);
        CP_COMMIT();
    }
    CP_WAIT(1);
    __syncwarp();

    // state: values v, scales c, edge factors f (all per-lane)
    float ve0 = (lane == 0) ? 1.0f : 0.0f;
    float vo0 = 0.f, ve1 = 0.f, vo1 = 0.f, ve64 = 0.f;
    float ce0 = 0.f, co0 = 0.f, ce1 = 0.f, co1 = 0.f, ce64v = 0.f;
    float f1e0 = (lane == 0) ? 0.f : 1.f;   // even[0] has no s-1 in-edge
    float f1o0 = 1.f, f2o0 = skm0;
    float f1e1 = 1.f, f1o1 = 1.f, f2o1 = skm1, fe64 = 1.f;

    // captured snapshot at t_idx
    float cv_e0 = 0.f, cv_o0 = 0.f, cv_e1 = 0.f, cv_o1 = 0.f, cv_e64 = 0.f;
    float cc_e0 = 0.f, cc_o0 = 0.f, cc_e1 = 0.f, cc_o1 = 0.f, cc_e64 = 0.f;

    const int mcap = t_idx >> 3;    // warp-uniform
    const int rcap = t_idx & 7;

    #define CTC_STEP(row)                                                        \
    {                                                                            \
        const float* __restrict__ _r = (row);                                    \
        float pb = _r[BLANK] + EPS_F;                                            \
        float p0 = _r[lab0] + EPS_F;                                             \
        float om0 = __shfl_up_sync(FM, vo0, 1);  /* lane0 garbage: f-masked */   \
        float ne0 = fmaf(f1e0, om0, ve0) * pb;                                   \
        float no0 = fmaf(f2o0, om0, fmaf(f1o0, ve0, vo0)) * p0;                  \
        if (TWO) {                                                               \
            float p1 = _r[lab1] + EPS_F;                                         \
            float o0t = __shfl_sync(FM, vo0, 31);                                \
            float om1 = __shfl_up_sync(FM, vo1, 1);                              \
            if (lane == 0) om1 = o0t;                                            \
            float ne1 = fmaf(f1e1, om1, ve1) * pb;                               \
            float no1 = fmaf(f2o1, om1, fmaf(f1o1, ve1, vo1)) * p1;              \
            if (E64) {                                                           \
                float o1t = __shfl_sync(FM, vo1, 31);                            \
                ve64 = fmaf(fe64, o1t, ve64) * pb;                               \
            }                                                                    \
            ve1 = ne1; vo1 = no1;                                                \
        }                                                                        \
        ve0 = ne0; vo0 = no0;                                                    \
    }

    for (int m = 0; m < NMACRO; ++m) {
        // issue macro m+2 (slot (m+2)%3, last read finished in iter m-1)
        if (m + 2 < NMACRO) {
            float* dst = &ring[(m + 2) % 3][0][0];
            const float* src = yb + (size_t)(m + 2) * MACRO * CTC_C;
            #pragma unroll
            for (int r = 0; r < MACRO; ++r)
                cp_async16(dst + r * CTC_C + lane * 4, src + r * CTC_C + lane * 4);
        }
        CP_COMMIT();

        const float (*rows)[CTC_C] = ring[m % 3];

        if (m == mcap) {        // warp-uniform
            #pragma unroll
            for (int r = 0; r < MACRO; ++r) {
                CTC_STEP(rows[r]);
                if (r == rcap) {
                    cv_e0 = ve0; cv_o0 = vo0; cv_e1 = ve1; cv_o1 = vo1; cv_e64 = ve64;
                    cc_e0 = ce0; cc_o0 = co0; cc_e1 = ce1; cc_o1 = co1; cc_e64 = ce64v;
                }
            }
        } else {
            #pragma unroll
            for (int r = 0; r < MACRO; ++r)
                CTC_STEP(rows[r]);
        }

        // ---- renorm: per-state scales = running max of L, minus BIAS ----
        {
            float Le0 = ce0 + __logf(ve0);
            float Lo0 = co0 + __logf(vo0);
            float R0  = warp_runmax(fmaxf(Le0, Lo0));
            float Rm0 = __shfl_up_sync(FM, R0, 1);         // lane0: own (over-scale ok)
            float nce0 = fmaxf(Rm0, Le0) - BIAS;
            float nco0 = R0 - BIAS;
            float com0 = __shfl_up_sync(FM, nco0, 1);      // lane0 garbage: masked
            f1e0 = (lane == 0) ? 0.f : __expf(com0 - nce0);
            f1o0 = __expf(nce0 - nco0);
            f2o0 = skm0 * __expf(com0 - nco0);
            ve0 = __expf(Le0 - nce0);
            vo0 = __expf(Lo0 - nco0);
            ce0 = nce0; co0 = nco0;

            if (TWO) {
                float Le1 = ce1 + __logf(ve1);
                float Lo1 = co1 + __logf(vo1);
                float R0_31 = __shfl_sync(FM, R0, 31);
                float R1 = fmaxf(warp_runmax(fmaxf(Le1, Lo1)), R0_31);
                float Rm1 = __shfl_up_sync(FM, R1, 1);     // lane0: own >= R0_31, ok
                float nce1 = fmaxf(Rm1, Le1) - BIAS;
                float nco1 = R1 - BIAS;
                float com1 = __shfl_up_sync(FM, nco1, 1);
                float co0_31 = __shfl_sync(FM, nco0, 31);
                if (lane == 0) com1 = co0_31;
                f1e1 = __expf(com1 - nce1);
                f1o1 = __expf(nce1 - nco1);
                f2o1 = skm1 * __expf(com1 - nco1);
                ve1 = __expf(Le1 - nce1);
                vo1 = __expf(Lo1 - nco1);
                ce1 = nce1; co1 = nco1;

                if (E64) {
                    float Le64 = ce64v + __logf(ve64);
                    float R1_31 = __shfl_sync(FM, R1, 31);
                    float nce64 = fmaxf(R1_31, Le64) - BIAS;
                    float co1_31 = __shfl_sync(FM, nco1, 31);
                    fe64 = __expf(co1_31 - nce64);
                    ve64 = __expf(Le64 - nce64);
                    ce64v = nce64;
                }
            }
        }

        CP_WAIT(1);             // macro m+1 resident
        __syncwarp();
    }
    #undef CTC_STEP

    // ---- extract loss = -logaddexp(L[2l], L[2l-1]) at t_idx ----
    float LLe0 = cc_e0 + __logf(cv_e0);
    float LLo0 = cc_o0 + __logf(cv_o0);
    float a_last, a_prev;
    if (E64) {
        a_last = cc_e64 + __logf(cv_e64);       // lane-invariant
    } else {
        float ev = LLe0;
        if (TWO) {
            float LLe1 = cc_e1 + __logf(cv_e1);
            ev = (l >= 32) ? LLe1 : LLe0;
        }
        a_last = __shfl_sync(FM, ev, l & 31);
    }
    {
        float ov = LLo0;
        if (TWO) {
            float LLo1 = cc_o1 + __logf(cv_o1);
            ov = ((l - 1) >= 32) ? LLo1 : LLo0;
        }
        a_prev = __shfl_sync(FM, ov, (l - 1) & 31);
    }
    if (lane == 0) {
        float mx = fmaxf(a_last, a_prev);
        *outp = -(mx + __logf(__expf(a_last - mx) + __expf(a_prev - mx)));
    }
}

__global__ __launch_bounds__(WPC * 32, 1)
void ctc_loss_kernel(const float* __restrict__ y_pred,
                     const int*   __restrict__ labels,
                     const int*   __restrict__ input_length,
                     const int*   __restrict__ label_length,
                     float*       __restrict__ out)
{
    __shared__ float rings[WPC][3][MACRO][CTC_C];   // 24 KB
    const int wid  = threadIdx.x >> 5;
    const int lane = threadIdx.x & 31;
    const int b = blockIdx.x * WPC + wid;
    const float* __restrict__ yb = y_pred + (size_t)b * CTC_T * CTC_C;

    const int l     = label_length[b];
    const int t_idx = input_length[b] - 1;

    const int lab0 = labels[b * CTC_L + lane];
    const int lab1 = labels[b * CTC_L + 32 + lane];
    const int lab0_31 = __shfl_sync(FM, lab0, 31);
    int lab0m = __shfl_up_sync(FM, lab0, 1);
    int lab1m = __shfl_up_sync(FM, lab1, 1);
    if (lane == 0) lab1m = lab0_31;
    const float skm0 = ((lane > 0) && (lab0 != lab0m)) ? 1.0f : 0.0f;
    const float skm1 = (lab1 != lab1m) ? 1.0f : 0.0f;

    if (l <= 31)
        ctc_warp<false, false>(yb, rings[wid], lane, l, t_idx, lab0, lab1, skm0, skm1, out + b);
    else if (l <= 63)
        ctc_warp<true, false>(yb, rings[wid], lane, l, t_idx, lab0, lab1, skm0, skm1, out + b);
    else
        ctc_warp<true, true>(yb, rings[wid], lane, l, t_idx, lab0, lab1, skm0, skm1, out + b);
}

extern "C" void kernel_launch(void* const* d_in, const int* in_sizes, int n_in,
                              void* d_out, int out_size) {
    const float* y_pred       = (const float*)d_in[0];
    const int*   labels       = (const int*)  d_in[1];
    const int*   input_length = (const int*)  d_in[2];
    const int*   label_length = (const int*)  d_in[3];
    float*       out          = (float*)d_out;

    ctc_loss_kernel<<<CTC_B / WPC, WPC * 32>>>(y_pred, labels, input_length, label_length, out);
}